// round 1
// baseline (speedup 1.0000x reference)
#include <cuda_runtime.h>
#include <math.h>

#define NN 6000
#define EE 192000
#define MAXDEG 128
#define BN_EPS 1e-5f

// ---------------- scratch (static device globals; no allocation) ----------------
__device__ int   g_cnt[NN];
__device__ int   g_slot[NN * MAXDEG];
__device__ float g_x0[NN * 64];
__device__ float g_agg[NN * 64];
__device__ float g_p1[NN * 64];
__device__ float g_p2[NN * 64];
__device__ float g_p3[NN * 4];
__device__ float g_e1[NN * 64];
__device__ float g_e2[NN * 64];
__device__ float g_e3[NN * 64];
__device__ float g_bnsum[64];
__device__ float g_bnsq[64];
__device__ float g_scale[64];
__device__ float g_shift[64];
__device__ float g_ssm[NN * 4];
__device__ int   g_am[NN];
__device__ float g_xemb[NN * 32];
__device__ float g_sx[4 * 192];
__device__ float g_sx2[4 * 16];

// ---------------- kernels ----------------

__global__ void k_zero_cnt() {
    int i = blockIdx.x * blockDim.x + threadIdx.x;
    if (i < NN) g_cnt[i] = 0;
}

__global__ void k_zero_bn() {
    int i = threadIdx.x;
    if (i < 64) { g_bnsum[i] = 0.f; g_bnsq[i] = 0.f; }
}

__global__ void k_zero_sx() {
    int i = threadIdx.x;
    if (i < 768) g_sx[i] = 0.f;
}

// Build padded adjacency list: slot[src][k] = dst for the k-th edge out of src.
__global__ void k_build(const int* __restrict__ ei) {
    int e = blockIdx.x * blockDim.x + threadIdx.x;
    if (e >= EE) return;
    int s = ei[e];
    int d = ei[EE + e];
    int pos = atomicAdd(&g_cnt[s], 1);
    if (pos < MAXDEG) g_slot[s * MAXDEG + pos] = d;
}

// x0 = emb_w[node_types]
__global__ void k_gather(const float* __restrict__ emb, const int* __restrict__ nt) {
    int idx = blockIdx.x * blockDim.x + threadIdx.x;
    if (idx < NN * 64) {
        int i = idx >> 6, c = idx & 63;
        g_x0[idx] = emb[nt[i] * 64 + c];
    }
}

// agg[i] = mean over out-edges of in[dst]   (one block per node, 64 threads = channels)
__global__ void k_agg(const float* __restrict__ in) {
    int i = blockIdx.x;
    int c = threadIdx.x;
    int cnt = g_cnt[i];
    if (cnt > MAXDEG) cnt = MAXDEG;
    const int* sl = &g_slot[i * MAXDEG];
    float acc = 0.f;
    int j = 0;
    for (; j + 4 <= cnt; j += 4) {
        int d0 = sl[j], d1 = sl[j + 1], d2 = sl[j + 2], d3 = sl[j + 3];
        acc += in[d0 * 64 + c];
        acc += in[d1 * 64 + c];
        acc += in[d2 * 64 + c];
        acc += in[d3 * 64 + c];
    }
    for (; j < cnt; j++) acc += in[sl[j] * 64 + c];
    g_agg[i * 64 + c] = (cnt > 0) ? acc * (1.f / (float)cnt) : 0.f;
}

// y = relu(agg @ wr^T + in @ wl^T + b), plus BN partial sums (per-channel sum & sumsq).
// block = 256 threads, 64 rows per block.
__global__ void k_gemm64(const float* __restrict__ xin,
                         const float* __restrict__ wr, const float* __restrict__ wl,
                         const float* __restrict__ bias, float* __restrict__ y) {
    __shared__ float wsr[64][65];
    __shared__ float wsl[64][65];
    __shared__ float rs[4][64];
    __shared__ float rq[4][64];
    int tid = threadIdx.x;
    for (int idx = tid; idx < 4096; idx += 256) {
        int c = idx >> 6, k = idx & 63;
        wsr[k][c] = wr[idx];
        wsl[k][c] = wl[idx];
    }
    __syncthreads();
    int c = tid & 63;
    int r0 = tid >> 6;
    int row0 = blockIdx.x * 64;
    float bb = bias[c];
    float bsum = 0.f, bsq = 0.f;
    for (int r = r0; r < 64; r += 4) {
        int gr = row0 + r;
        if (gr >= NN) continue;
        const float* ar = &g_agg[gr * 64];
        const float* xr = &xin[gr * 64];
        float acc = bb;
#pragma unroll
        for (int k = 0; k < 64; k++)
            acc += ar[k] * wsr[k][c] + xr[k] * wsl[k][c];
        acc = fmaxf(acc, 0.f);
        y[gr * 64 + c] = acc;
        bsum += acc;
        bsq += acc * acc;
    }
    rs[r0][c] = bsum;
    rq[r0][c] = bsq;
    __syncthreads();
    if (r0 == 0) {
        float s = rs[0][c] + rs[1][c] + rs[2][c] + rs[3][c];
        float q = rq[0][c] + rq[1][c] + rq[2][c] + rq[3][c];
        atomicAdd(&g_bnsum[c], s);
        atomicAdd(&g_bnsq[c], q);
    }
}

// Cout=4 variant (pool layer 3)
__global__ void k_gemm4(const float* __restrict__ xin,
                        const float* __restrict__ wr, const float* __restrict__ wl,
                        const float* __restrict__ bias, float* __restrict__ y) {
    __shared__ float wsr[64][5];
    __shared__ float wsl[64][5];
    __shared__ float red_s[4];
    __shared__ float red_q[4];
    int tid = threadIdx.x;
    if (tid < 4) { red_s[tid] = 0.f; red_q[tid] = 0.f; }
    for (int idx = tid; idx < 256; idx += 256) {
        int c = idx >> 6, k = idx & 63;
        wsr[k][c] = wr[idx];
        wsl[k][c] = wl[idx];
    }
    __syncthreads();
    int c = tid & 3;
    int r = tid >> 2;
    int gr = blockIdx.x * 64 + r;
    float acc = 0.f;
    if (gr < NN) {
        acc = bias[c];
        const float* ar = &g_agg[gr * 64];
        const float* xr = &xin[gr * 64];
#pragma unroll
        for (int k = 0; k < 64; k++)
            acc += ar[k] * wsr[k][c] + xr[k] * wsl[k][c];
        acc = fmaxf(acc, 0.f);
        y[gr * 4 + c] = acc;
        atomicAdd(&red_s[c], acc);
        atomicAdd(&red_q[c], acc * acc);
    }
    __syncthreads();
    if (tid < 4) {
        atomicAdd(&g_bnsum[tid], red_s[tid]);
        atomicAdd(&g_bnsq[tid], red_q[tid]);
    }
}

__global__ void k_bnfin(int C) {
    int c = threadIdx.x;
    if (c < C) {
        float m = g_bnsum[c] * (1.f / (float)NN);
        float v = g_bnsq[c] * (1.f / (float)NN) - m * m;
        v = fmaxf(v, 0.f);
        float sc = rsqrtf(v + BN_EPS);
        g_scale[c] = sc;
        g_shift[c] = -m * sc;
    }
}

__global__ void k_bnapply(float* __restrict__ y, int mask, int total) {
    int idx = blockIdx.x * blockDim.x + threadIdx.x;
    if (idx < total) {
        int c = idx & mask;
        y[idx] = y[idx] * g_scale[c] + g_shift[c];
    }
}

// pool lin over concat(p1,p2,p3) -> relu -> softmax + argmax.  one warp per node.
__global__ void k_poollin(const float* __restrict__ plw, const float* __restrict__ plb) {
    int gw = (blockIdx.x * blockDim.x + threadIdx.x) >> 5;
    int lane = threadIdx.x & 31;
    if (gw >= NN) return;
    int i = gw;
    float a0 = 0.f, a1 = 0.f, a2 = 0.f, a3 = 0.f;
    for (int k = lane; k < 64; k += 32) {
        float v1 = g_p1[i * 64 + k];
        float v2 = g_p2[i * 64 + k];
        a0 += v1 * plw[0 * 132 + k] + v2 * plw[0 * 132 + 64 + k];
        a1 += v1 * plw[1 * 132 + k] + v2 * plw[1 * 132 + 64 + k];
        a2 += v1 * plw[2 * 132 + k] + v2 * plw[2 * 132 + 64 + k];
        a3 += v1 * plw[3 * 132 + k] + v2 * plw[3 * 132 + 64 + k];
    }
    if (lane < 4) {
        float v3 = g_p3[i * 4 + lane];
        a0 += v3 * plw[0 * 132 + 128 + lane];
        a1 += v3 * plw[1 * 132 + 128 + lane];
        a2 += v3 * plw[2 * 132 + 128 + lane];
        a3 += v3 * plw[3 * 132 + 128 + lane];
    }
#pragma unroll
    for (int o = 16; o > 0; o >>= 1) {
        a0 += __shfl_xor_sync(0xFFFFFFFFu, a0, o);
        a1 += __shfl_xor_sync(0xFFFFFFFFu, a1, o);
        a2 += __shfl_xor_sync(0xFFFFFFFFu, a2, o);
        a3 += __shfl_xor_sync(0xFFFFFFFFu, a3, o);
    }
    if (lane == 0) {
        float s0 = fmaxf(a0 + plb[0], 0.f);
        float s1 = fmaxf(a1 + plb[1], 0.f);
        float s2 = fmaxf(a2 + plb[2], 0.f);
        float s3 = fmaxf(a3 + plb[3], 0.f);
        int am = 0; float best = s0;
        if (s1 > best) { best = s1; am = 1; }
        if (s2 > best) { best = s2; am = 2; }
        if (s3 > best) { best = s3; am = 3; }
        g_am[i] = am;
        float e0 = expf(s0 - best), e1 = expf(s1 - best),
              e2 = expf(s2 - best), e3 = expf(s3 - best);
        float inv = 1.f / (e0 + e1 + e2 + e3);
        g_ssm[i * 4 + 0] = e0 * inv;
        g_ssm[i * 4 + 1] = e1 * inv;
        g_ssm[i * 4 + 2] = e2 * inv;
        g_ssm[i * 4 + 3] = e3 * inv;
    }
}

// x_embed = concat(e1,e2,e3) @ embl_w^T + embl_b     [N,192] -> [N,32]
__global__ void k_xembed(const float* __restrict__ w, const float* __restrict__ b) {
    __shared__ float ws[192][33];
    int tid = threadIdx.x;
    for (int idx = tid; idx < 6144; idx += 256) {
        int c = idx / 192, k = idx % 192;
        ws[k][c] = w[idx];
    }
    __syncthreads();
    int c = tid & 31;
    int r0 = tid >> 5;
    int row0 = blockIdx.x * 64;
    for (int r = r0; r < 64; r += 8) {
        int gr = row0 + r;
        if (gr >= NN) continue;
        float acc = b[c];
        const float* s1 = &g_e1[gr * 64];
        const float* s2 = &g_e2[gr * 64];
        const float* s3 = &g_e3[gr * 64];
#pragma unroll
        for (int k = 0; k < 64; k++) acc += s1[k] * ws[k][c];
#pragma unroll
        for (int k = 0; k < 64; k++) acc += s2[k] * ws[64 + k][c];
#pragma unroll
        for (int k = 0; k < 64; k++) acc += s3[k] * ws[128 + k][c];
        g_xemb[gr * 32 + c] = acc;
    }
}

// s_x = softmax(S)^T @ XE    -> [4,192], accumulated with atomics
__global__ void k_sxacc() {
    int c = threadIdx.x;  // 0..191
    int n0 = blockIdx.x * 125;
    const float* src = (c < 64) ? g_e1 : (c < 128) ? g_e2 : g_e3;
    int co = (c < 64) ? c : (c < 128) ? (c - 64) : (c - 128);
    float a0 = 0.f, a1 = 0.f, a2 = 0.f, a3 = 0.f;
    for (int n = n0; n < n0 + 125; n++) {
        float s0 = g_ssm[n * 4 + 0];
        float s1 = g_ssm[n * 4 + 1];
        float s2 = g_ssm[n * 4 + 2];
        float s3 = g_ssm[n * 4 + 3];
        float v = src[n * 64 + co];
        a0 += s0 * v; a1 += s1 * v; a2 += s2 * v; a3 += s3 * v;
    }
    atomicAdd(&g_sx[0 * 192 + c], a0);
    atomicAdd(&g_sx[1 * 192 + c], a1);
    atomicAdd(&g_sx[2 * 192 + c], a2);
    atomicAdd(&g_sx[3 * 192 + c], a3);
}

// s_x -> relu(lin1) -> lin2 -> g_sx2[4,16]    (single block)
__global__ void k_head(const float* __restrict__ l1w, const float* __restrict__ l1b,
                       const float* __restrict__ l2w, const float* __restrict__ l2b) {
    __shared__ float t1[4][64];
    int tid = threadIdx.x;  // 256
    int j = tid >> 6, c = tid & 63;
    float acc = l1b[c];
#pragma unroll 8
    for (int k = 0; k < 192; k++) acc += g_sx[j * 192 + k] * l1w[c * 192 + k];
    t1[j][c] = fmaxf(acc, 0.f);
    __syncthreads();
    if (tid < 64) {
        int jj = tid >> 4, cc = tid & 15;
        float a = l2b[cc];
#pragma unroll
        for (int k = 0; k < 64; k++) a += t1[jj][k] * l2w[cc * 64 + k];
        g_sx2[jj * 16 + cc] = a;
    }
}

// out[i] = lin3( concat(x_embed[i], sx2[argmax[i]]) )
__global__ void k_final(const float* __restrict__ l3w, const float* __restrict__ l3b,
                        float* __restrict__ out) {
    __shared__ float w[768];
    __shared__ float b[16];
    __shared__ float sx2[64];
    int tid = threadIdx.x;  // 256
    for (int idx = tid; idx < 768; idx += 256) w[idx] = l3w[idx];
    if (tid < 16) b[tid] = l3b[tid];
    if (tid < 64) sx2[tid] = g_sx2[tid];
    __syncthreads();
    int c = tid & 15;
    int ln = tid >> 4;
    int i = blockIdx.x * 16 + ln;
    int am = g_am[i];
    float acc = b[c];
    const float* xe = &g_xemb[i * 32];
#pragma unroll
    for (int k = 0; k < 32; k++) acc += xe[k] * w[c * 48 + k];
#pragma unroll
    for (int k = 0; k < 16; k++) acc += sx2[am * 16 + k] * w[c * 48 + 32 + k];
    out[i * 16 + c] = acc;
}

// ---------------- host ----------------

extern "C" void kernel_launch(void* const* d_in, const int* in_sizes, int n_in,
                              void* d_out, int out_size) {
    const int* ei = nullptr;
    const int* nt = nullptr;
    const float* P[29];
    int np = 0;
    for (int i = 0; i < n_in; i++) {
        if (in_sizes[i] == 2 * EE)      ei = (const int*)d_in[i];
        else if (in_sizes[i] == NN)     nt = (const int*)d_in[i];
        else if (np < 29)               P[np++] = (const float*)d_in[i];
    }
    if (!ei || !nt || np != 29) return;

    const float *emb  = P[0];
    const float *pw1r = P[1],  *pw1l = P[2],  *pb1 = P[3];
    const float *pw2r = P[4],  *pw2l = P[5],  *pb2 = P[6];
    const float *pw3r = P[7],  *pw3l = P[8],  *pb3 = P[9];
    const float *plw  = P[10], *plb  = P[11];
    const float *ew1r = P[12], *ew1l = P[13], *eb1 = P[14];
    const float *ew2r = P[15], *ew2l = P[16], *eb2 = P[17];
    const float *ew3r = P[18], *ew3l = P[19], *eb3 = P[20];
    const float *l1w  = P[21], *l1b  = P[22];
    const float *l2w  = P[23], *l2b  = P[24];
    const float *emblw = P[25], *emblb = P[26];
    const float *l3w  = P[27], *l3b  = P[28];
    float* out = (float*)d_out;

    static float *p_x0 = nullptr, *p_p1, *p_p2, *p_p3, *p_e1, *p_e2, *p_e3;
    if (!p_x0) {
        cudaGetSymbolAddress((void**)&p_x0, g_x0);
        cudaGetSymbolAddress((void**)&p_p1, g_p1);
        cudaGetSymbolAddress((void**)&p_p2, g_p2);
        cudaGetSymbolAddress((void**)&p_p3, g_p3);
        cudaGetSymbolAddress((void**)&p_e1, g_e1);
        cudaGetSymbolAddress((void**)&p_e2, g_e2);
        cudaGetSymbolAddress((void**)&p_e3, g_e3);
    }

    const int GB64 = (NN + 63) / 64;  // 94

    // adjacency + embedding gather
    k_zero_cnt<<<(NN + 255) / 256, 256>>>();
    k_build<<<EE / 256, 256>>>(ei);
    k_gather<<<(NN * 64 + 255) / 256, 256>>>(emb, nt);

    // SAGE layer (64ch): optional agg, then fused dual-GEMM+ReLU+BN
    auto layer64 = [&](const float* in, const float* wr, const float* wl,
                       const float* b, float* y, bool do_agg) {
        if (do_agg) k_agg<<<NN, 64>>>(in);
        k_zero_bn<<<1, 64>>>();
        k_gemm64<<<GB64, 256>>>(in, wr, wl, b, y);
        k_bnfin<<<1, 64>>>(64);
        k_bnapply<<<(NN * 64 + 255) / 256, 256>>>(y, 63, NN * 64);
    };

    // pool L1 and embed L1 share agg(x0)
    layer64(p_x0, pw1r, pw1l, pb1, p_p1, true);
    layer64(p_x0, ew1r, ew1l, eb1, p_e1, false);

    // pool L2
    layer64(p_p1, pw2r, pw2l, pb2, p_p2, true);

    // pool L3 (Cout=4)
    k_agg<<<NN, 64>>>(p_p2);
    k_zero_bn<<<1, 64>>>();
    k_gemm4<<<GB64, 256>>>(p_p2, pw3r, pw3l, pb3, p_p3);
    k_bnfin<<<1, 64>>>(4);
    k_bnapply<<<(NN * 4 + 255) / 256, 256>>>(p_p3, 3, NN * 4);

    // embed L2, L3
    layer64(p_e1, ew2r, ew2l, eb2, p_e2, true);
    layer64(p_e2, ew3r, ew3l, eb3, p_e3, true);

    // pool assignment: s -> softmax + argmax
    k_poollin<<<NN / 8, 256>>>(plw, plb);

    // x_embed
    k_xembed<<<GB64, 256>>>(emblw, emblb);

    // pooled features s_x = ssm^T @ xe
    k_zero_sx<<<1, 768>>>();
    k_sxacc<<<48, 192>>>();

    // s_x -> lin1 -> lin2
    k_head<<<1, 256>>>(l1w, l1b, l2w, l2b);

    // final output
    k_final<<<NN / 16, 256>>>(l3w, l3b, out);
}

// round 2
// speedup vs baseline: 2.0269x; 2.0269x over previous
#include <cuda_runtime.h>
#include <math.h>

#define NN 6000
#define EE 192000
#define MAXDEG 128
#define BN_EPS 1e-5f
#define GB64 94              // ceil(NN/64)
#define NNINV (1.0f/6000.0f)

// ---------------- scratch (static device globals) ----------------
__device__ int   g_cnt[NN];
__device__ int   g_slot[NN * MAXDEG];
__device__ float g_x0[NN * 64];
__device__ float g_p1[NN * 64];   // RAW (pre-BN) activations
__device__ float g_p2[NN * 64];
__device__ float g_p3[NN * 4];
__device__ float g_e1[NN * 64];
__device__ float g_e2[NN * 64];
__device__ float g_e3[NN * 64];
__device__ float g_stats[6][2][64];   // [layer: p1,p2,p3,e1,e2,e3][sum,sq][c]
__device__ float g_ssm[NN * 4];
__device__ int   g_am[NN];
__device__ float g_xemb[NN * 32];
__device__ float g_sx[4 * 192];
__device__ float g_sx2[4 * 16];

// BN coefficient from accumulated stats: y' = s*y + t
__device__ __forceinline__ void bn_coef(int slot, int c, float& s, float& t) {
    float m = g_stats[slot][0][c] * NNINV;
    float v = g_stats[slot][1][c] * NNINV - m * m;
    float sc = rsqrtf(fmaxf(v, 0.f) + BN_EPS);
    s = sc; t = -m * sc;
}

// ---------------- setup kernels ----------------

__global__ void k_init() {
    int i = blockIdx.x * 256 + threadIdx.x;
    if (i < NN) g_cnt[i] = 0;
    else if (i < NN + 768) ((float*)g_stats)[i - NN] = 0.f;
    else if (i < NN + 1536) g_sx[i - NN - 768] = 0.f;
}

__global__ void k_build_gather(const int* __restrict__ ei,
                               const float* __restrict__ emb,
                               const int* __restrict__ nt) {
    int b = blockIdx.x;
    if (b < 750) {
        int e = b * 256 + threadIdx.x;
        int s = ei[e], d = ei[EE + e];
        int pos = atomicAdd(&g_cnt[s], 1);
        if (pos < MAXDEG) g_slot[s * MAXDEG + pos] = d;
    } else {
        int idx = (b - 750) * 256 + threadIdx.x;   // < NN*64
        int i = idx >> 6, c = idx & 63;
        g_x0[idx] = emb[nt[i] * 64 + c];
    }
}

// ---------------- fused layer kernels ----------------
// Layer 1: input x0 (no BN), shared agg, dual output (p1, e1) + stats.
__global__ void k_layer1(const float* __restrict__ pwr, const float* __restrict__ pwl,
                         const float* __restrict__ pb,
                         const float* __restrict__ ewr, const float* __restrict__ ewl,
                         const float* __restrict__ eb) {
    extern __shared__ float dsm[];
    float* ash = dsm;                // [64k][68r]
    float* xsh = dsm + 4352;
    float* wpr = dsm + 2 * 4352;     // [64k][68c]
    float* wpl = dsm + 3 * 4352;
    float* wer = dsm + 4 * 4352;
    float* wel = dsm + 5 * 4352;
    __shared__ float bp[64], be[64], sum_p[64], sq_p[64], sum_e[64], sq_e[64];

    int tid = threadIdx.x;
    int row0 = blockIdx.x * 64;

    for (int idx = tid; idx < 4096; idx += 256) {
        int c = idx >> 6, k = idx & 63;
        wpr[k * 68 + c] = pwr[idx];
        wpl[k * 68 + c] = pwl[idx];
        wer[k * 68 + c] = ewr[idx];
        wel[k * 68 + c] = ewl[idx];
    }
    if (tid < 64) {
        bp[tid] = pb[tid]; be[tid] = eb[tid];
        sum_p[tid] = 0.f; sq_p[tid] = 0.f; sum_e[tid] = 0.f; sq_e[tid] = 0.f;
    }
    __syncthreads();

    // ---- agg (identity BN) into ash (transposed), x0 into xsh ----
    {
        int r = tid >> 2, q = tid & 3;
        int gr = row0 + r;
        int cnt = 0;
        if (gr < NN) { cnt = g_cnt[gr]; if (cnt > MAXDEG) cnt = MAXDEG; }
        const int* sl = g_slot + (size_t)(gr < NN ? gr : 0) * MAXDEG;
        float4 a0 = {0,0,0,0}, a1 = {0,0,0,0}, a2 = {0,0,0,0}, a3 = {0,0,0,0};
        int j = 0;
        for (; j + 2 <= cnt; j += 2) {
            const float4* b0 = (const float4*)(g_x0 + (size_t)sl[j] * 64 + q * 16);
            const float4* b1 = (const float4*)(g_x0 + (size_t)sl[j+1] * 64 + q * 16);
            float4 u0 = b0[0], u1 = b0[1], u2 = b0[2], u3 = b0[3];
            float4 v0 = b1[0], v1 = b1[1], v2 = b1[2], v3 = b1[3];
            a0.x+=u0.x+v0.x; a0.y+=u0.y+v0.y; a0.z+=u0.z+v0.z; a0.w+=u0.w+v0.w;
            a1.x+=u1.x+v1.x; a1.y+=u1.y+v1.y; a1.z+=u1.z+v1.z; a1.w+=u1.w+v1.w;
            a2.x+=u2.x+v2.x; a2.y+=u2.y+v2.y; a2.z+=u2.z+v2.z; a2.w+=u2.w+v2.w;
            a3.x+=u3.x+v3.x; a3.y+=u3.y+v3.y; a3.z+=u3.z+v3.z; a3.w+=u3.w+v3.w;
        }
        if (j < cnt) {
            const float4* b0 = (const float4*)(g_x0 + (size_t)sl[j] * 64 + q * 16);
            float4 u0 = b0[0], u1 = b0[1], u2 = b0[2], u3 = b0[3];
            a0.x+=u0.x; a0.y+=u0.y; a0.z+=u0.z; a0.w+=u0.w;
            a1.x+=u1.x; a1.y+=u1.y; a1.z+=u1.z; a1.w+=u1.w;
            a2.x+=u2.x; a2.y+=u2.y; a2.z+=u2.z; a2.w+=u2.w;
            a3.x+=u3.x; a3.y+=u3.y; a3.z+=u3.z; a3.w+=u3.w;
        }
        float inv = (cnt > 0) ? 1.f / (float)cnt : 0.f;
        int k0 = q * 16;
        ash[(k0+ 0)*68+r]=a0.x*inv; ash[(k0+ 1)*68+r]=a0.y*inv; ash[(k0+ 2)*68+r]=a0.z*inv; ash[(k0+ 3)*68+r]=a0.w*inv;
        ash[(k0+ 4)*68+r]=a1.x*inv; ash[(k0+ 5)*68+r]=a1.y*inv; ash[(k0+ 6)*68+r]=a1.z*inv; ash[(k0+ 7)*68+r]=a1.w*inv;
        ash[(k0+ 8)*68+r]=a2.x*inv; ash[(k0+ 9)*68+r]=a2.y*inv; ash[(k0+10)*68+r]=a2.z*inv; ash[(k0+11)*68+r]=a2.w*inv;
        ash[(k0+12)*68+r]=a3.x*inv; ash[(k0+13)*68+r]=a3.y*inv; ash[(k0+14)*68+r]=a3.z*inv; ash[(k0+15)*68+r]=a3.w*inv;
    }
    for (int idx = tid; idx < 4096; idx += 256) {
        int k = idx & 63, rr = idx >> 6;
        int g = row0 + rr;
        xsh[k * 68 + rr] = (g < NN) ? g_x0[(size_t)g * 64 + k] : 0.f;
    }
    __syncthreads();

    // ---- dual GEMM 4x4 tiles ----
    int cg = tid & 15, rg = tid >> 4;
    int c4 = cg * 4, r4 = rg * 4;
    float accp[4][4] = {}, acce[4][4] = {};
#pragma unroll 8
    for (int k = 0; k < 64; k++) {
        float4 av = *(const float4*)&ash[k * 68 + r4];
        float4 xv = *(const float4*)&xsh[k * 68 + r4];
        float4 pr = *(const float4*)&wpr[k * 68 + c4];
        float4 pl = *(const float4*)&wpl[k * 68 + c4];
        float4 er = *(const float4*)&wer[k * 68 + c4];
        float4 el = *(const float4*)&wel[k * 68 + c4];
        float aa[4] = {av.x, av.y, av.z, av.w};
        float xx[4] = {xv.x, xv.y, xv.z, xv.w};
        float prr[4] = {pr.x, pr.y, pr.z, pr.w};
        float pll[4] = {pl.x, pl.y, pl.z, pl.w};
        float err_[4] = {er.x, er.y, er.z, er.w};
        float ell[4] = {el.x, el.y, el.z, el.w};
#pragma unroll
        for (int ri = 0; ri < 4; ri++)
#pragma unroll
            for (int ci = 0; ci < 4; ci++) {
                accp[ri][ci] = fmaf(aa[ri], prr[ci], fmaf(xx[ri], pll[ci], accp[ri][ci]));
                acce[ri][ci] = fmaf(aa[ri], err_[ci], fmaf(xx[ri], ell[ci], acce[ri][ci]));
            }
    }
    float psum[4] = {}, psq[4] = {}, esum[4] = {}, esq[4] = {};
#pragma unroll
    for (int ri = 0; ri < 4; ri++) {
        int gr = row0 + r4 + ri;
        if (gr >= NN) continue;
        float4 op, oe;
        float vp0 = fmaxf(accp[ri][0] + bp[c4+0], 0.f), vp1 = fmaxf(accp[ri][1] + bp[c4+1], 0.f);
        float vp2 = fmaxf(accp[ri][2] + bp[c4+2], 0.f), vp3 = fmaxf(accp[ri][3] + bp[c4+3], 0.f);
        float ve0 = fmaxf(acce[ri][0] + be[c4+0], 0.f), ve1 = fmaxf(acce[ri][1] + be[c4+1], 0.f);
        float ve2 = fmaxf(acce[ri][2] + be[c4+2], 0.f), ve3 = fmaxf(acce[ri][3] + be[c4+3], 0.f);
        op.x=vp0; op.y=vp1; op.z=vp2; op.w=vp3;
        oe.x=ve0; oe.y=ve1; oe.z=ve2; oe.w=ve3;
        *(float4*)&g_p1[(size_t)gr * 64 + c4] = op;
        *(float4*)&g_e1[(size_t)gr * 64 + c4] = oe;
        psum[0]+=vp0; psum[1]+=vp1; psum[2]+=vp2; psum[3]+=vp3;
        psq[0]+=vp0*vp0; psq[1]+=vp1*vp1; psq[2]+=vp2*vp2; psq[3]+=vp3*vp3;
        esum[0]+=ve0; esum[1]+=ve1; esum[2]+=ve2; esum[3]+=ve3;
        esq[0]+=ve0*ve0; esq[1]+=ve1*ve1; esq[2]+=ve2*ve2; esq[3]+=ve3*ve3;
    }
#pragma unroll
    for (int ci = 0; ci < 4; ci++) {
        atomicAdd(&sum_p[c4+ci], psum[ci]); atomicAdd(&sq_p[c4+ci], psq[ci]);
        atomicAdd(&sum_e[c4+ci], esum[ci]); atomicAdd(&sq_e[c4+ci], esq[ci]);
    }
    __syncthreads();
    if (tid < 64) {
        atomicAdd(&g_stats[0][0][tid], sum_p[tid]); atomicAdd(&g_stats[0][1][tid], sq_p[tid]);
        atomicAdd(&g_stats[3][0][tid], sum_e[tid]); atomicAdd(&g_stats[3][1][tid], sq_e[tid]);
    }
}

// Pair of independent layer jobs in one launch. Job A: cout=64 (blocks 0..93).
// Job B: cout=coutB (blocks 94..187). Input BN applied on the fly from stats.
__global__ void __launch_bounds__(256, 2)
k_pair(const float* inA, int sAin, const float* wrA, const float* wlA,
       const float* bA, float* outA, int sAout,
       const float* inB, int sBin, const float* wrB, const float* wlB,
       const float* bB, float* outB, int sBout, int coutB) {
    bool isA = blockIdx.x < GB64;
    int blk = isA ? blockIdx.x : blockIdx.x - GB64;
    const float* in = isA ? inA : inB;
    int s_in  = isA ? sAin : sBin;
    const float* wr = isA ? wrA : wrB;
    const float* wl = isA ? wlA : wlB;
    const float* bias = isA ? bA : bB;
    float* out = isA ? outA : outB;
    int s_out = isA ? sAout : sBout;
    int cout  = isA ? 64 : coutB;

    extern __shared__ float dsm[];
    float* ash = dsm;
    float* xsh = dsm + 4352;
    float* wrs = dsm + 2 * 4352;
    float* wls = dsm + 3 * 4352;
    __shared__ float sc[64], tc[64], bsh[64], ssum[64], ssq[64];

    int tid = threadIdx.x;
    int row0 = blk * 64;

    if (tid < 64) {
        float s, t; bn_coef(s_in, tid, s, t);
        sc[tid] = s; tc[tid] = t;
        ssum[tid] = 0.f; ssq[tid] = 0.f;
        if (tid < cout) bsh[tid] = bias[tid];
    }
    int wtot = cout * 64;
    for (int idx = tid; idx < wtot; idx += 256) {
        int c = idx >> 6, k = idx & 63;
        wrs[k * 68 + c] = wr[idx];
        wls[k * 68 + c] = wl[idx];
    }
    __syncthreads();

    // ---- agg with input BN ----
    {
        int r = tid >> 2, q = tid & 3;
        int gr = row0 + r;
        int cnt = 0;
        if (gr < NN) { cnt = g_cnt[gr]; if (cnt > MAXDEG) cnt = MAXDEG; }
        const int* sl = g_slot + (size_t)(gr < NN ? gr : 0) * MAXDEG;
        float4 a0 = {0,0,0,0}, a1 = {0,0,0,0}, a2 = {0,0,0,0}, a3 = {0,0,0,0};
        int j = 0;
        for (; j + 2 <= cnt; j += 2) {
            const float4* b0 = (const float4*)(in + (size_t)sl[j] * 64 + q * 16);
            const float4* b1 = (const float4*)(in + (size_t)sl[j+1] * 64 + q * 16);
            float4 u0 = b0[0], u1 = b0[1], u2 = b0[2], u3 = b0[3];
            float4 v0 = b1[0], v1 = b1[1], v2 = b1[2], v3 = b1[3];
            a0.x+=u0.x+v0.x; a0.y+=u0.y+v0.y; a0.z+=u0.z+v0.z; a0.w+=u0.w+v0.w;
            a1.x+=u1.x+v1.x; a1.y+=u1.y+v1.y; a1.z+=u1.z+v1.z; a1.w+=u1.w+v1.w;
            a2.x+=u2.x+v2.x; a2.y+=u2.y+v2.y; a2.z+=u2.z+v2.z; a2.w+=u2.w+v2.w;
            a3.x+=u3.x+v3.x; a3.y+=u3.y+v3.y; a3.z+=u3.z+v3.z; a3.w+=u3.w+v3.w;
        }
        if (j < cnt) {
            const float4* b0 = (const float4*)(in + (size_t)sl[j] * 64 + q * 16);
            float4 u0 = b0[0], u1 = b0[1], u2 = b0[2], u3 = b0[3];
            a0.x+=u0.x; a0.y+=u0.y; a0.z+=u0.z; a0.w+=u0.w;
            a1.x+=u1.x; a1.y+=u1.y; a1.z+=u1.z; a1.w+=u1.w;
            a2.x+=u2.x; a2.y+=u2.y; a2.z+=u2.z; a2.w+=u2.w;
            a3.x+=u3.x; a3.y+=u3.y; a3.z+=u3.z; a3.w+=u3.w;
        }
        int k0 = q * 16;
        float vals[16] = {a0.x,a0.y,a0.z,a0.w, a1.x,a1.y,a1.z,a1.w,
                          a2.x,a2.y,a2.z,a2.w, a3.x,a3.y,a3.z,a3.w};
        if (cnt > 0) {
            float inv = 1.f / (float)cnt;
#pragma unroll
            for (int u = 0; u < 16; u++)
                ash[(k0+u)*68 + r] = fmaf(vals[u]*inv, sc[k0+u], tc[k0+u]);
        } else {
#pragma unroll
            for (int u = 0; u < 16; u++) ash[(k0+u)*68 + r] = 0.f;
        }
    }
    for (int idx = tid; idx < 4096; idx += 256) {
        int k = idx & 63, rr = idx >> 6;
        int g = row0 + rr;
        xsh[k * 68 + rr] = (g < NN) ? fmaf(in[(size_t)g * 64 + k], sc[k], tc[k]) : 0.f;
    }
    __syncthreads();

    if (cout == 64) {
        int cg = tid & 15, rg = tid >> 4;
        int c4 = cg * 4, r4 = rg * 4;
        float acc[4][4] = {};
#pragma unroll 16
        for (int k = 0; k < 64; k++) {
            float4 av = *(const float4*)&ash[k * 68 + r4];
            float4 xv = *(const float4*)&xsh[k * 68 + r4];
            float4 wrv = *(const float4*)&wrs[k * 68 + c4];
            float4 wlv = *(const float4*)&wls[k * 68 + c4];
            float aa[4] = {av.x, av.y, av.z, av.w};
            float xx[4] = {xv.x, xv.y, xv.z, xv.w};
            float wr_[4] = {wrv.x, wrv.y, wrv.z, wrv.w};
            float wl_[4] = {wlv.x, wlv.y, wlv.z, wlv.w};
#pragma unroll
            for (int ri = 0; ri < 4; ri++)
#pragma unroll
                for (int ci = 0; ci < 4; ci++)
                    acc[ri][ci] = fmaf(aa[ri], wr_[ci], fmaf(xx[ri], wl_[ci], acc[ri][ci]));
        }
        float csum[4] = {}, csq[4] = {};
#pragma unroll
        for (int ri = 0; ri < 4; ri++) {
            int gr = row0 + r4 + ri;
            if (gr >= NN) continue;
            float v0 = fmaxf(acc[ri][0] + bsh[c4+0], 0.f);
            float v1 = fmaxf(acc[ri][1] + bsh[c4+1], 0.f);
            float v2 = fmaxf(acc[ri][2] + bsh[c4+2], 0.f);
            float v3 = fmaxf(acc[ri][3] + bsh[c4+3], 0.f);
            float4 o; o.x=v0; o.y=v1; o.z=v2; o.w=v3;
            *(float4*)&out[(size_t)gr * 64 + c4] = o;
            csum[0]+=v0; csum[1]+=v1; csum[2]+=v2; csum[3]+=v3;
            csq[0]+=v0*v0; csq[1]+=v1*v1; csq[2]+=v2*v2; csq[3]+=v3*v3;
        }
#pragma unroll
        for (int ci = 0; ci < 4; ci++) {
            atomicAdd(&ssum[c4+ci], csum[ci]);
            atomicAdd(&ssq[c4+ci], csq[ci]);
        }
        __syncthreads();
        if (tid < 64) {
            atomicAdd(&g_stats[s_out][0][tid], ssum[tid]);
            atomicAdd(&g_stats[s_out][1][tid], ssq[tid]);
        }
    } else {
        // cout == 4
        int rr = tid >> 2, c = tid & 3;
        int gr = row0 + rr;
        float acc = 0.f;
#pragma unroll 16
        for (int k = 0; k < 64; k++)
            acc = fmaf(ash[k*68+rr], wrs[k*68+c], fmaf(xsh[k*68+rr], wls[k*68+c], acc));
        if (gr < NN) {
            float v = fmaxf(acc + bsh[c], 0.f);
            out[(size_t)gr * 4 + c] = v;
            atomicAdd(&ssum[c], v);
            atomicAdd(&ssq[c], v * v);
        }
        __syncthreads();
        if (tid < 4) {
            atomicAdd(&g_stats[s_out][0][tid], ssum[tid]);
            atomicAdd(&g_stats[s_out][1][tid], ssq[tid]);
        }
    }
}

// ---------------- pool assignment + x_embed (one launch) ----------------
__global__ void k_pool_xemb(const float* __restrict__ plw, const float* __restrict__ plb,
                            const float* __restrict__ ew, const float* __restrict__ eb) {
    __shared__ float ws[192 * 33];
    __shared__ float s1[64], t1[64], s2[64], t2[64], s3[4], t3[4];
    __shared__ float se[192], te[192];
    int tid = threadIdx.x;

    if (blockIdx.x < 750) {
        // ---- pool lin + softmax + argmax ----
        if (tid < 64)       { float s,t; bn_coef(0, tid, s, t);      s1[tid]=s; t1[tid]=t; }
        else if (tid < 128) { float s,t; bn_coef(1, tid-64, s, t);   s2[tid-64]=s; t2[tid-64]=t; }
        else if (tid < 132) { float s,t; bn_coef(2, tid-128, s, t);  s3[tid-128]=s; t3[tid-128]=t; }
        __syncthreads();
        int i = blockIdx.x * 8 + (tid >> 5);
        int lane = tid & 31;
        float a0 = 0.f, a1 = 0.f, a2 = 0.f, a3 = 0.f;
        for (int k = lane; k < 64; k += 32) {
            float v1 = fmaf(g_p1[(size_t)i*64+k], s1[k], t1[k]);
            float v2 = fmaf(g_p2[(size_t)i*64+k], s2[k], t2[k]);
            a0 += v1 * plw[0*132+k] + v2 * plw[0*132+64+k];
            a1 += v1 * plw[1*132+k] + v2 * plw[1*132+64+k];
            a2 += v1 * plw[2*132+k] + v2 * plw[2*132+64+k];
            a3 += v1 * plw[3*132+k] + v2 * plw[3*132+64+k];
        }
        if (lane < 4) {
            float v3 = fmaf(g_p3[(size_t)i*4+lane], s3[lane], t3[lane]);
            a0 += v3 * plw[0*132+128+lane];
            a1 += v3 * plw[1*132+128+lane];
            a2 += v3 * plw[2*132+128+lane];
            a3 += v3 * plw[3*132+128+lane];
        }
#pragma unroll
        for (int o = 16; o > 0; o >>= 1) {
            a0 += __shfl_xor_sync(0xFFFFFFFFu, a0, o);
            a1 += __shfl_xor_sync(0xFFFFFFFFu, a1, o);
            a2 += __shfl_xor_sync(0xFFFFFFFFu, a2, o);
            a3 += __shfl_xor_sync(0xFFFFFFFFu, a3, o);
        }
        if (lane == 0) {
            float q0 = fmaxf(a0 + plb[0], 0.f), q1 = fmaxf(a1 + plb[1], 0.f);
            float q2 = fmaxf(a2 + plb[2], 0.f), q3 = fmaxf(a3 + plb[3], 0.f);
            int am = 0; float best = q0;
            if (q1 > best) { best = q1; am = 1; }
            if (q2 > best) { best = q2; am = 2; }
            if (q3 > best) { best = q3; am = 3; }
            g_am[i] = am;
            float e0 = expf(q0-best), e1 = expf(q1-best), e2 = expf(q2-best), e3 = expf(q3-best);
            float inv = 1.f / (e0+e1+e2+e3);
            g_ssm[i*4+0] = e0*inv; g_ssm[i*4+1] = e1*inv;
            g_ssm[i*4+2] = e2*inv; g_ssm[i*4+3] = e3*inv;
        }
    } else {
        // ---- x_embed = BN(e1|e2|e3) @ embl_w^T + embl_b ----
        if (tid < 192) {
            float s, t; bn_coef(3 + tid / 64, tid & 63, s, t);
            se[tid] = s; te[tid] = t;
        }
        for (int idx = tid; idx < 6144; idx += 256) {
            int c = idx / 192, k = idx % 192;
            ws[k * 33 + c] = ew[idx];
        }
        __syncthreads();
        int blk = blockIdx.x - 750;
        int c = tid & 31, r0t = tid >> 5;
        int row0 = blk * 64;
        for (int r = r0t; r < 64; r += 8) {
            int gr = row0 + r;
            if (gr >= NN) continue;
            float acc = eb[c];
            const float* p1 = &g_e1[(size_t)gr * 64];
            const float* p2 = &g_e2[(size_t)gr * 64];
            const float* p3 = &g_e3[(size_t)gr * 64];
#pragma unroll 8
            for (int k = 0; k < 64; k++) {
                acc = fmaf(fmaf(p1[k], se[k],     te[k]),     ws[k*33+c],       acc);
                acc = fmaf(fmaf(p2[k], se[64+k],  te[64+k]),  ws[(64+k)*33+c],  acc);
                acc = fmaf(fmaf(p3[k], se[128+k], te[128+k]), ws[(128+k)*33+c], acc);
            }
            g_xemb[(size_t)gr * 32 + c] = acc;
        }
    }
}

// s_x = softmax(S)^T @ BN(XE)  -> [4,192]
__global__ void k_sxacc() {
    int c = threadIdx.x;                  // 0..191
    int slot = 3 + c / 64, co = c & 63;
    float s, t; bn_coef(slot, co, s, t);
    const float* src = (c < 64) ? g_e1 : (c < 128) ? g_e2 : g_e3;
    int n0 = blockIdx.x * 125;
    float a0 = 0.f, a1 = 0.f, a2 = 0.f, a3 = 0.f;
    for (int n = n0; n < n0 + 125; n++) {
        float w0 = g_ssm[n*4+0], w1 = g_ssm[n*4+1], w2 = g_ssm[n*4+2], w3 = g_ssm[n*4+3];
        float v = fmaf(src[(size_t)n * 64 + co], s, t);
        a0 = fmaf(w0, v, a0); a1 = fmaf(w1, v, a1);
        a2 = fmaf(w2, v, a2); a3 = fmaf(w3, v, a3);
    }
    atomicAdd(&g_sx[0*192+c], a0);
    atomicAdd(&g_sx[1*192+c], a1);
    atomicAdd(&g_sx[2*192+c], a2);
    atomicAdd(&g_sx[3*192+c], a3);
}

__global__ void k_head(const float* __restrict__ l1w, const float* __restrict__ l1b,
                       const float* __restrict__ l2w, const float* __restrict__ l2b) {
    __shared__ float t1[4][64];
    int tid = threadIdx.x;
    int j = tid >> 6, c = tid & 63;
    float acc = l1b[c];
#pragma unroll 8
    for (int k = 0; k < 192; k++) acc = fmaf(g_sx[j*192+k], l1w[c*192+k], acc);
    t1[j][c] = fmaxf(acc, 0.f);
    __syncthreads();
    if (tid < 64) {
        int jj = tid >> 4, cc = tid & 15;
        float a = l2b[cc];
#pragma unroll
        for (int k = 0; k < 64; k++) a = fmaf(t1[jj][k], l2w[cc*64+k], a);
        g_sx2[jj*16+cc] = a;
    }
}

__global__ void k_final(const float* __restrict__ l3w, const float* __restrict__ l3b,
                        float* __restrict__ out) {
    __shared__ float w[768];
    __shared__ float b[16];
    __shared__ float sx2[64];
    int tid = threadIdx.x;
    for (int idx = tid; idx < 768; idx += 256) w[idx] = l3w[idx];
    if (tid < 16) b[tid] = l3b[tid];
    if (tid < 64) sx2[tid] = g_sx2[tid];
    __syncthreads();
    int c = tid & 15, ln = tid >> 4;
    int i = blockIdx.x * 16 + ln;
    int am = g_am[i];
    float acc = b[c];
    const float* xe = &g_xemb[(size_t)i * 32];
#pragma unroll
    for (int k = 0; k < 32; k++) acc = fmaf(xe[k], w[c*48+k], acc);
#pragma unroll
    for (int k = 0; k < 16; k++) acc = fmaf(sx2[am*16+k], w[c*48+32+k], acc);
    out[(size_t)i * 16 + c] = acc;
}

// ---------------- host ----------------

extern "C" void kernel_launch(void* const* d_in, const int* in_sizes, int n_in,
                              void* d_out, int out_size) {
    const int* ei = nullptr;
    const int* nt = nullptr;
    const float* P[29];
    int np = 0;
    for (int i = 0; i < n_in; i++) {
        if (in_sizes[i] == 2 * EE)      ei = (const int*)d_in[i];
        else if (in_sizes[i] == NN)     nt = (const int*)d_in[i];
        else if (np < 29)               P[np++] = (const float*)d_in[i];
    }
    if (!ei || !nt || np != 29) return;

    const float *emb  = P[0];
    const float *pw1r = P[1],  *pw1l = P[2],  *pb1 = P[3];
    const float *pw2r = P[4],  *pw2l = P[5],  *pb2 = P[6];
    const float *pw3r = P[7],  *pw3l = P[8],  *pb3 = P[9];
    const float *plw  = P[10], *plb  = P[11];
    const float *ew1r = P[12], *ew1l = P[13], *eb1 = P[14];
    const float *ew2r = P[15], *ew2l = P[16], *eb2 = P[17];
    const float *ew3r = P[18], *ew3l = P[19], *eb3 = P[20];
    const float *l1w  = P[21], *l1b  = P[22];
    const float *l2w  = P[23], *l2b  = P[24];
    const float *emblw = P[25], *emblb = P[26];
    const float *l3w  = P[27], *l3b  = P[28];
    float* out = (float*)d_out;

    static float *p_p1 = nullptr, *p_p2, *p_p3, *p_e1, *p_e2, *p_e3;
    if (!p_p1) {
        cudaGetSymbolAddress((void**)&p_p1, g_p1);
        cudaGetSymbolAddress((void**)&p_p2, g_p2);
        cudaGetSymbolAddress((void**)&p_p3, g_p3);
        cudaGetSymbolAddress((void**)&p_e1, g_e1);
        cudaGetSymbolAddress((void**)&p_e2, g_e2);
        cudaGetSymbolAddress((void**)&p_e3, g_e3);
        cudaFuncSetAttribute(k_layer1, cudaFuncAttributeMaxDynamicSharedMemorySize, 6 * 4352 * 4);
        cudaFuncSetAttribute(k_pair,   cudaFuncAttributeMaxDynamicSharedMemorySize, 4 * 4352 * 4);
    }

    k_init<<<30, 256>>>();
    k_build_gather<<<2250, 256>>>(ei, emb, nt);
    k_layer1<<<GB64, 256, 6 * 4352 * 4>>>(pw1r, pw1l, pb1, ew1r, ew1l, eb1);
    k_pair<<<2 * GB64, 256, 4 * 4352 * 4>>>(p_p1, 0, pw2r, pw2l, pb2, p_p2, 1,
                                            p_e1, 3, ew2r, ew2l, eb2, p_e2, 4, 64);
    k_pair<<<2 * GB64, 256, 4 * 4352 * 4>>>(p_e2, 4, ew3r, ew3l, eb3, p_e3, 5,
                                            p_p2, 1, pw3r, pw3l, pb3, p_p3, 2, 4);
    k_pool_xemb<<<750 + GB64, 256>>>(plw, plb, emblw, emblb);
    k_sxacc<<<48, 192>>>();
    k_head<<<1, 256>>>(l1w, l1b, l2w, l2b);
    k_final<<<NN / 16, 256>>>(l3w, l3b, out);
}

// round 3
// speedup vs baseline: 2.0966x; 1.0344x over previous
#include <cuda_runtime.h>
#include <math.h>

#define NN 6000
#define EE 192000
#define MAXDEG 128
#define BN_EPS 1e-5f
#define GB32 188             // ceil(NN/32)
#define GB64 94
#define NNINV (1.0f/6000.0f)

// smem layout (floats): ash[64*33] xsh[64*33] wrs[64*68] wls[64*68]
#define ASTR 33
#define WSTR 68
#define SM_ASH 0
#define SM_XSH 2112
#define SM_WRS 4224
#define SM_WLS 8576
#define SM_TOT 12928         // floats = 51712 bytes

// ---------------- scratch ----------------
__device__ int   g_cnt[NN];
__device__ int   g_slot[NN * MAXDEG];
__device__ float g_x0[NN * 64];
__device__ float g_p1[NN * 64];   // RAW (pre-BN) activations
__device__ float g_p2[NN * 64];
__device__ float g_p3[NN * 4];
__device__ float g_e1[NN * 64];
__device__ float g_e2[NN * 64];
__device__ float g_e3[NN * 64];
__device__ float g_stats[6][2][64];
__device__ float g_ssm[NN * 4];
__device__ int   g_am[NN];
__device__ float g_xemb[NN * 32];
__device__ float g_sx[4 * 192];
__device__ float g_sx2[4 * 16];

__device__ __forceinline__ void bn_coef(int slot, int c, float& s, float& t) {
    float m = g_stats[slot][0][c] * NNINV;
    float v = g_stats[slot][1][c] * NNINV - m * m;
    float sc = rsqrtf(fmaxf(v, 0.f) + BN_EPS);
    s = sc; t = -m * sc;
}

// ---------------- setup ----------------
__global__ void k_init() {
    int i = blockIdx.x * 256 + threadIdx.x;
    if (i < NN) g_cnt[i] = 0;
    else if (i < NN + 768) ((float*)g_stats)[i - NN] = 0.f;
    else if (i < NN + 1536) g_sx[i - NN - 768] = 0.f;
}

__global__ void k_build_gather(const int* __restrict__ ei,
                               const float* __restrict__ emb,
                               const int* __restrict__ nt) {
    int b = blockIdx.x;
    if (b < 750) {
        int e = b * 256 + threadIdx.x;
        int s = ei[e], d = ei[EE + e];
        int pos = atomicAdd(&g_cnt[s], 1);
        if (pos < MAXDEG) g_slot[s * MAXDEG + pos] = d;
    } else {
        int idx = (b - 750) * 256 + threadIdx.x;
        int i = idx >> 6, c = idx & 63;
        g_x0[idx] = emb[nt[i] * 64 + c];
    }
}

// ---------------- fused SAGE layer, 32-row tiles, paired jobs ----------------
// blocks [0, GB32): job A (cout=64). blocks [GB32, 2*GB32): job B (cout=coutB).
// s_in < 0 means identity input BN.
__global__ void __launch_bounds__(256, 3)
k_pair(const float* inA, int sAin, const float* wrA, const float* wlA,
       const float* bA, float* outA, int sAout,
       const float* inB, int sBin, const float* wrB, const float* wlB,
       const float* bB, float* outB, int sBout, int coutB) {
    bool isA = blockIdx.x < GB32;
    int blk = isA ? blockIdx.x : blockIdx.x - GB32;
    const float* in = isA ? inA : inB;
    int s_in  = isA ? sAin : sBin;
    const float* wr = isA ? wrA : wrB;
    const float* wl = isA ? wlA : wlB;
    const float* bias = isA ? bA : bB;
    float* out = isA ? outA : outB;
    int s_out = isA ? sAout : sBout;
    int cout  = isA ? 64 : coutB;

    extern __shared__ float sm[];
    float* ash = sm + SM_ASH;
    float* xsh = sm + SM_XSH;
    float* wrs = sm + SM_WRS;
    float* wls = sm + SM_WLS;
    __shared__ float sc[64], tc[64], bsh[64], ssum[64], ssq[64];

    int tid = threadIdx.x;
    int row0 = blk * 32;

    if (tid < 64) {
        float s = 1.f, t = 0.f;
        if (s_in >= 0) bn_coef(s_in, tid, s, t);
        sc[tid] = s; tc[tid] = t;
        ssum[tid] = 0.f; ssq[tid] = 0.f;
        if (tid < cout) bsh[tid] = bias[tid];
    }
    for (int idx = tid; idx < cout * 64; idx += 256) {
        int c = idx >> 6, k = idx & 63;
        wrs[k * WSTR + c] = wr[idx];
        wls[k * WSTR + c] = wl[idx];
    }
    __syncthreads();

    // ---- agg (BN'd) into ash: 8 threads per row, 8 channels each ----
    {
        int r = tid >> 3;            // 0..31
        int q = tid & 7;             // channel group
        int gr = row0 + r;
        int cnt = 0;
        if (gr < NN) { cnt = g_cnt[gr]; if (cnt > MAXDEG) cnt = MAXDEG; }
        const int* sl = g_slot + (size_t)(gr < NN ? gr : 0) * MAXDEG;
        int choff = q * 8;
        float4 a0 = {0,0,0,0}, a1 = {0,0,0,0};
        int j = 0;
        for (; j + 2 <= cnt; j += 2) {
            const float4* p0 = (const float4*)(in + (size_t)sl[j]   * 64 + choff);
            const float4* p1 = (const float4*)(in + (size_t)sl[j+1] * 64 + choff);
            float4 u0 = p0[0], u1 = p0[1];
            float4 v0 = p1[0], v1 = p1[1];
            a0.x += u0.x + v0.x; a0.y += u0.y + v0.y;
            a0.z += u0.z + v0.z; a0.w += u0.w + v0.w;
            a1.x += u1.x + v1.x; a1.y += u1.y + v1.y;
            a1.z += u1.z + v1.z; a1.w += u1.w + v1.w;
        }
        if (j < cnt) {
            const float4* p0 = (const float4*)(in + (size_t)sl[j] * 64 + choff);
            float4 u0 = p0[0], u1 = p0[1];
            a0.x += u0.x; a0.y += u0.y; a0.z += u0.z; a0.w += u0.w;
            a1.x += u1.x; a1.y += u1.y; a1.z += u1.z; a1.w += u1.w;
        }
        float inv = (cnt > 0) ? 1.f / (float)cnt : 0.f;
        float vals[8] = {a0.x, a0.y, a0.z, a0.w, a1.x, a1.y, a1.z, a1.w};
#pragma unroll
        for (int u = 0; u < 8; u++) {
            int ch = choff + u;
            ash[ch * ASTR + r] = fmaf(vals[u] * inv, sc[ch], tc[ch]);
        }
    }
    // ---- x (BN'd) into xsh, coalesced ----
    for (int idx = tid; idx < 2048; idx += 256) {
        int k = idx & 63, rr = idx >> 6;
        int g = row0 + rr;
        xsh[k * ASTR + rr] = (g < NN) ? fmaf(in[(size_t)g * 64 + k], sc[k], tc[k]) : 0.f;
    }
    __syncthreads();

    if (cout == 64) {
        int cg = tid & 15, rg = tid >> 4;   // 16 colgroups x 16 rowgroups
        int c4 = cg * 4, r2 = rg * 2;
        float acc[2][4] = {};
#pragma unroll 4
        for (int k = 0; k < 64; k++) {
            float a0 = ash[k * ASTR + r2];
            float a1 = ash[k * ASTR + r2 + 1];
            float x0 = xsh[k * ASTR + r2];
            float x1 = xsh[k * ASTR + r2 + 1];
            float4 w4 = *(const float4*)&wrs[k * WSTR + c4];
            float4 l4 = *(const float4*)&wls[k * WSTR + c4];
            acc[0][0] = fmaf(a0, w4.x, fmaf(x0, l4.x, acc[0][0]));
            acc[0][1] = fmaf(a0, w4.y, fmaf(x0, l4.y, acc[0][1]));
            acc[0][2] = fmaf(a0, w4.z, fmaf(x0, l4.z, acc[0][2]));
            acc[0][3] = fmaf(a0, w4.w, fmaf(x0, l4.w, acc[0][3]));
            acc[1][0] = fmaf(a1, w4.x, fmaf(x1, l4.x, acc[1][0]));
            acc[1][1] = fmaf(a1, w4.y, fmaf(x1, l4.y, acc[1][1]));
            acc[1][2] = fmaf(a1, w4.z, fmaf(x1, l4.z, acc[1][2]));
            acc[1][3] = fmaf(a1, w4.w, fmaf(x1, l4.w, acc[1][3]));
        }
        float csum[4] = {}, csq[4] = {};
#pragma unroll
        for (int ri = 0; ri < 2; ri++) {
            int gr = row0 + r2 + ri;
            if (gr >= NN) continue;
            float v0 = fmaxf(acc[ri][0] + bsh[c4+0], 0.f);
            float v1 = fmaxf(acc[ri][1] + bsh[c4+1], 0.f);
            float v2 = fmaxf(acc[ri][2] + bsh[c4+2], 0.f);
            float v3 = fmaxf(acc[ri][3] + bsh[c4+3], 0.f);
            float4 o; o.x = v0; o.y = v1; o.z = v2; o.w = v3;
            *(float4*)&out[(size_t)gr * 64 + c4] = o;
            csum[0] += v0; csum[1] += v1; csum[2] += v2; csum[3] += v3;
            csq[0] += v0*v0; csq[1] += v1*v1; csq[2] += v2*v2; csq[3] += v3*v3;
        }
#pragma unroll
        for (int ci = 0; ci < 4; ci++) {
            atomicAdd(&ssum[c4+ci], csum[ci]);
            atomicAdd(&ssq[c4+ci], csq[ci]);
        }
        __syncthreads();
        if (tid < 64) {
            atomicAdd(&g_stats[s_out][0][tid], ssum[tid]);
            atomicAdd(&g_stats[s_out][1][tid], ssq[tid]);
        }
    } else {
        // cout == 4: 32 rows x 4 cols = 128 active threads
        if (tid < 128) {
            int r = tid >> 2, c = tid & 3;
            int gr = row0 + r;
            float acc = 0.f;
#pragma unroll 8
            for (int k = 0; k < 64; k++)
                acc = fmaf(ash[k*ASTR+r], wrs[k*WSTR+c],
                      fmaf(xsh[k*ASTR+r], wls[k*WSTR+c], acc));
            if (gr < NN) {
                float v = fmaxf(acc + bsh[c], 0.f);
                out[(size_t)gr * 4 + c] = v;
                atomicAdd(&ssum[c], v);
                atomicAdd(&ssq[c], v * v);
            }
        }
        __syncthreads();
        if (tid < 4) {
            atomicAdd(&g_stats[s_out][0][tid], ssum[tid]);
            atomicAdd(&g_stats[s_out][1][tid], ssq[tid]);
        }
    }
}

// ---------------- pool assignment + x_embed ----------------
__global__ void k_pool_xemb(const float* __restrict__ plw, const float* __restrict__ plb,
                            const float* __restrict__ ew, const float* __restrict__ eb) {
    __shared__ float ws[192 * 33];
    __shared__ float s1[64], t1[64], s2[64], t2[64], s3[4], t3[4];
    __shared__ float se[192], te[192];
    int tid = threadIdx.x;

    if (blockIdx.x < 750) {
        if (tid < 64)       { float s,t; bn_coef(0, tid, s, t);      s1[tid]=s; t1[tid]=t; }
        else if (tid < 128) { float s,t; bn_coef(1, tid-64, s, t);   s2[tid-64]=s; t2[tid-64]=t; }
        else if (tid < 132) { float s,t; bn_coef(2, tid-128, s, t);  s3[tid-128]=s; t3[tid-128]=t; }
        __syncthreads();
        int i = blockIdx.x * 8 + (tid >> 5);
        int lane = tid & 31;
        float a0 = 0.f, a1 = 0.f, a2 = 0.f, a3 = 0.f;
        for (int k = lane; k < 64; k += 32) {
            float v1 = fmaf(g_p1[(size_t)i*64+k], s1[k], t1[k]);
            float v2 = fmaf(g_p2[(size_t)i*64+k], s2[k], t2[k]);
            a0 += v1 * plw[0*132+k] + v2 * plw[0*132+64+k];
            a1 += v1 * plw[1*132+k] + v2 * plw[1*132+64+k];
            a2 += v1 * plw[2*132+k] + v2 * plw[2*132+64+k];
            a3 += v1 * plw[3*132+k] + v2 * plw[3*132+64+k];
        }
        if (lane < 4) {
            float v3 = fmaf(g_p3[(size_t)i*4+lane], s3[lane], t3[lane]);
            a0 += v3 * plw[0*132+128+lane];
            a1 += v3 * plw[1*132+128+lane];
            a2 += v3 * plw[2*132+128+lane];
            a3 += v3 * plw[3*132+128+lane];
        }
#pragma unroll
        for (int o = 16; o > 0; o >>= 1) {
            a0 += __shfl_xor_sync(0xFFFFFFFFu, a0, o);
            a1 += __shfl_xor_sync(0xFFFFFFFFu, a1, o);
            a2 += __shfl_xor_sync(0xFFFFFFFFu, a2, o);
            a3 += __shfl_xor_sync(0xFFFFFFFFu, a3, o);
        }
        if (lane == 0) {
            float q0 = fmaxf(a0 + plb[0], 0.f), q1 = fmaxf(a1 + plb[1], 0.f);
            float q2 = fmaxf(a2 + plb[2], 0.f), q3 = fmaxf(a3 + plb[3], 0.f);
            int am = 0; float best = q0;
            if (q1 > best) { best = q1; am = 1; }
            if (q2 > best) { best = q2; am = 2; }
            if (q3 > best) { best = q3; am = 3; }
            g_am[i] = am;
            float e0 = expf(q0-best), e1 = expf(q1-best), e2 = expf(q2-best), e3 = expf(q3-best);
            float inv = 1.f / (e0+e1+e2+e3);
            g_ssm[i*4+0] = e0*inv; g_ssm[i*4+1] = e1*inv;
            g_ssm[i*4+2] = e2*inv; g_ssm[i*4+3] = e3*inv;
        }
    } else {
        if (tid < 192) {
            float s, t; bn_coef(3 + tid / 64, tid & 63, s, t);
            se[tid] = s; te[tid] = t;
        }
        for (int idx = tid; idx < 6144; idx += 256) {
            int c = idx / 192, k = idx % 192;
            ws[k * 33 + c] = ew[idx];
        }
        __syncthreads();
        int blk = blockIdx.x - 750;
        int c = tid & 31, r0t = tid >> 5;
        int row0 = blk * 64;
        for (int r = r0t; r < 64; r += 8) {
            int gr = row0 + r;
            if (gr >= NN) continue;
            float acc = eb[c];
            const float* p1 = &g_e1[(size_t)gr * 64];
            const float* p2 = &g_e2[(size_t)gr * 64];
            const float* p3 = &g_e3[(size_t)gr * 64];
#pragma unroll 8
            for (int k = 0; k < 64; k++) {
                acc = fmaf(fmaf(p1[k], se[k],     te[k]),     ws[k*33+c],       acc);
                acc = fmaf(fmaf(p2[k], se[64+k],  te[64+k]),  ws[(64+k)*33+c],  acc);
                acc = fmaf(fmaf(p3[k], se[128+k], te[128+k]), ws[(128+k)*33+c], acc);
            }
            g_xemb[(size_t)gr * 32 + c] = acc;
        }
    }
}

__global__ void k_sxacc() {
    int c = threadIdx.x;
    int slot = 3 + c / 64, co = c & 63;
    float s, t; bn_coef(slot, co, s, t);
    const float* src = (c < 64) ? g_e1 : (c < 128) ? g_e2 : g_e3;
    int n0 = blockIdx.x * 125;
    float a0 = 0.f, a1 = 0.f, a2 = 0.f, a3 = 0.f;
    for (int n = n0; n < n0 + 125; n++) {
        float w0 = g_ssm[n*4+0], w1 = g_ssm[n*4+1], w2 = g_ssm[n*4+2], w3 = g_ssm[n*4+3];
        float v = fmaf(src[(size_t)n * 64 + co], s, t);
        a0 = fmaf(w0, v, a0); a1 = fmaf(w1, v, a1);
        a2 = fmaf(w2, v, a2); a3 = fmaf(w3, v, a3);
    }
    atomicAdd(&g_sx[0*192+c], a0);
    atomicAdd(&g_sx[1*192+c], a1);
    atomicAdd(&g_sx[2*192+c], a2);
    atomicAdd(&g_sx[3*192+c], a3);
}

__global__ void k_head(const float* __restrict__ l1w, const float* __restrict__ l1b,
                       const float* __restrict__ l2w, const float* __restrict__ l2b) {
    __shared__ float t1[4][64];
    int tid = threadIdx.x;
    int j = tid >> 6, c = tid & 63;
    float acc = l1b[c];
#pragma unroll 8
    for (int k = 0; k < 192; k++) acc = fmaf(g_sx[j*192+k], l1w[c*192+k], acc);
    t1[j][c] = fmaxf(acc, 0.f);
    __syncthreads();
    if (tid < 64) {
        int jj = tid >> 4, cc = tid & 15;
        float a = l2b[cc];
#pragma unroll
        for (int k = 0; k < 64; k++) a = fmaf(t1[jj][k], l2w[cc*64+k], a);
        g_sx2[jj*16+cc] = a;
    }
}

__global__ void k_final(const float* __restrict__ l3w, const float* __restrict__ l3b,
                        float* __restrict__ out) {
    __shared__ float w[768];
    __shared__ float b[16];
    __shared__ float sx2[64];
    int tid = threadIdx.x;
    for (int idx = tid; idx < 768; idx += 256) w[idx] = l3w[idx];
    if (tid < 16) b[tid] = l3b[tid];
    if (tid < 64) sx2[tid] = g_sx2[tid];
    __syncthreads();
    int c = tid & 15, ln = tid >> 4;
    int i = blockIdx.x * 16 + ln;
    int am = g_am[i];
    float acc = b[c];
    const float* xe = &g_xemb[(size_t)i * 32];
#pragma unroll
    for (int k = 0; k < 32; k++) acc = fmaf(xe[k], w[c*48+k], acc);
#pragma unroll
    for (int k = 0; k < 16; k++) acc = fmaf(sx2[am*16+k], w[c*48+32+k], acc);
    out[(size_t)i * 16 + c] = acc;
}

// ---------------- host ----------------
extern "C" void kernel_launch(void* const* d_in, const int* in_sizes, int n_in,
                              void* d_out, int out_size) {
    const int* ei = nullptr;
    const int* nt = nullptr;
    const float* P[29];
    int np = 0;
    for (int i = 0; i < n_in; i++) {
        if (in_sizes[i] == 2 * EE)      ei = (const int*)d_in[i];
        else if (in_sizes[i] == NN)     nt = (const int*)d_in[i];
        else if (np < 29)               P[np++] = (const float*)d_in[i];
    }
    if (!ei || !nt || np != 29) return;

    const float *emb  = P[0];
    const float *pw1r = P[1],  *pw1l = P[2],  *pb1 = P[3];
    const float *pw2r = P[4],  *pw2l = P[5],  *pb2 = P[6];
    const float *pw3r = P[7],  *pw3l = P[8],  *pb3 = P[9];
    const float *plw  = P[10], *plb  = P[11];
    const float *ew1r = P[12], *ew1l = P[13], *eb1 = P[14];
    const float *ew2r = P[15], *ew2l = P[16], *eb2 = P[17];
    const float *ew3r = P[18], *ew3l = P[19], *eb3 = P[20];
    const float *l1w  = P[21], *l1b  = P[22];
    const float *l2w  = P[23], *l2b  = P[24];
    const float *emblw = P[25], *emblb = P[26];
    const float *l3w  = P[27], *l3b  = P[28];
    float* out = (float*)d_out;

    static float *p_x0 = nullptr, *p_p1, *p_p2, *p_p3, *p_e1, *p_e2, *p_e3;
    if (!p_x0) {
        cudaGetSymbolAddress((void**)&p_x0, g_x0);
        cudaGetSymbolAddress((void**)&p_p1, g_p1);
        cudaGetSymbolAddress((void**)&p_p2, g_p2);
        cudaGetSymbolAddress((void**)&p_p3, g_p3);
        cudaGetSymbolAddress((void**)&p_e1, g_e1);
        cudaGetSymbolAddress((void**)&p_e2, g_e2);
        cudaGetSymbolAddress((void**)&p_e3, g_e3);
        cudaFuncSetAttribute(k_pair, cudaFuncAttributeMaxDynamicSharedMemorySize, SM_TOT * 4);
    }

    k_init<<<30, 256>>>();
    k_build_gather<<<2250, 256>>>(ei, emb, nt);
    // layer 1 (both branches, identity input BN)
    k_pair<<<2 * GB32, 256, SM_TOT * 4>>>(p_x0, -1, pw1r, pw1l, pb1, p_p1, 0,
                                          p_x0, -1, ew1r, ew1l, eb1, p_e1, 3, 64);
    // layer 2 (pool + embed)
    k_pair<<<2 * GB32, 256, SM_TOT * 4>>>(p_p1, 0, pw2r, pw2l, pb2, p_p2, 1,
                                          p_e1, 3, ew2r, ew2l, eb2, p_e2, 4, 64);
    // layer 3 (embed cout=64 + pool cout=4)
    k_pair<<<2 * GB32, 256, SM_TOT * 4>>>(p_e2, 4, ew3r, ew3l, eb3, p_e3, 5,
                                          p_p2, 1, pw3r, pw3l, pb3, p_p3, 2, 4);
    k_pool_xemb<<<750 + GB64, 256>>>(plw, plb, emblw, emblb);
    k_sxacc<<<48, 192>>>();
    k_head<<<1, 256>>>(l1w, l1b, l2w, l2b);
    k_final<<<NN / 16, 256>>>(l3w, l3b, out);
}

// round 5
// speedup vs baseline: 2.3708x; 1.1308x over previous
#include <cuda_runtime.h>
#include <math.h>

#define NN 6000
#define EE 192000
#define MAXDEG 128
#define BN_EPS 1e-5f
#define TR 16                // rows per tile
#define GB16 375             // NN / TR
#define GB64 94
#define NNINV (1.0f/6000.0f)
#define ASTR 17              // smem stride for 16-row tiles

// ---------------- scratch ----------------
__device__ int   g_cnt[NN];
__device__ int   g_slot[NN * MAXDEG];
__device__ float g_x0[NN * 64];
__device__ float g_p1[NN * 64];   // RAW (pre-BN) activations
__device__ float g_p2[NN * 64];
__device__ float g_p3[NN * 4];
__device__ float g_e1[NN * 64];
__device__ float g_e2[NN * 64];
__device__ float g_e3[NN * 64];
__device__ float g_wt[10 * 4096]; // transposed 64x64 weights: [k][c]
__device__ float g_stats[6][2][64];
__device__ float g_ssm[NN * 4];
__device__ int   g_am[NN];
__device__ float g_xemb[NN * 32];
__device__ float g_sx[4 * 192];
__device__ float g_sx2[4 * 16];

__device__ __forceinline__ void bn_coef(int slot, int c, float& s, float& t) {
    float m = g_stats[slot][0][c] * NNINV;
    float v = g_stats[slot][1][c] * NNINV - m * m;
    float sc = rsqrtf(fmaxf(v, 0.f) + BN_EPS);
    s = sc; t = -m * sc;
}

// ---------------- setup: zero + weight transpose ----------------
// blocks [0,30): zero counters/stats/sx. blocks [30,190): transpose 10 weight mats.
__global__ void k_init(const float* w0, const float* w1, const float* w2,
                       const float* w3, const float* w4, const float* w5,
                       const float* w6, const float* w7, const float* w8,
                       const float* w9) {
    int b = blockIdx.x;
    if (b < 30) {
        int i = b * 256 + threadIdx.x;
        if (i < NN) g_cnt[i] = 0;
        else if (i < NN + 768) ((float*)g_stats)[i - NN] = 0.f;
        else if (i < NN + 1536) g_sx[i - NN - 768] = 0.f;
    } else {
        const float* srcs[10] = {w0, w1, w2, w3, w4, w5, w6, w7, w8, w9};
        int bb = b - 30;
        int m = bb >> 4;
        int idx = ((bb & 15) * 256) + threadIdx.x;   // output index, [k][c]
        int k = idx >> 6, c = idx & 63;
        g_wt[m * 4096 + idx] = srcs[m][c * 64 + k];
    }
}

__global__ void k_build_gather(const int* __restrict__ ei,
                               const float* __restrict__ emb,
                               const int* __restrict__ nt) {
    int b = blockIdx.x;
    if (b < 750) {
        int e = b * 256 + threadIdx.x;
        int s = ei[e], d = ei[EE + e];
        int pos = atomicAdd(&g_cnt[s], 1);
        if (pos < MAXDEG) g_slot[s * MAXDEG + pos] = d;
    } else {
        int idx = (b - 750) * 256 + threadIdx.x;
        int i = idx >> 6, c = idx & 63;
        g_x0[idx] = emb[nt[i] * 64 + c];
    }
}

// ---------------- shared agg helper (16 rows, 128 threads, 8 thr/row) ----------
__device__ __forceinline__ void agg_tile(const float* __restrict__ in, int row0,
                                         float* ash, const float* sc, const float* tc,
                                         int tid) {
    int r = tid >> 3;            // 0..15
    int q = tid & 7;             // channel group
    int gr = row0 + r;
    int cnt = g_cnt[gr];
    if (cnt > MAXDEG) cnt = MAXDEG;
    const int* sl = g_slot + (size_t)gr * MAXDEG;
    int choff = q * 8;
    float4 a0 = {0,0,0,0}, a1 = {0,0,0,0};
    int j = 0;
    for (; j + 2 <= cnt; j += 2) {
        const float4* p0 = (const float4*)(in + (size_t)sl[j]   * 64 + choff);
        const float4* p1 = (const float4*)(in + (size_t)sl[j+1] * 64 + choff);
        float4 u0 = p0[0], u1 = p0[1];
        float4 v0 = p1[0], v1 = p1[1];
        a0.x += u0.x + v0.x; a0.y += u0.y + v0.y;
        a0.z += u0.z + v0.z; a0.w += u0.w + v0.w;
        a1.x += u1.x + v1.x; a1.y += u1.y + v1.y;
        a1.z += u1.z + v1.z; a1.w += u1.w + v1.w;
    }
    if (j < cnt) {
        const float4* p0 = (const float4*)(in + (size_t)sl[j] * 64 + choff);
        float4 u0 = p0[0], u1 = p0[1];
        a0.x += u0.x; a0.y += u0.y; a0.z += u0.z; a0.w += u0.w;
        a1.x += u1.x; a1.y += u1.y; a1.z += u1.z; a1.w += u1.w;
    }
    float vals[8] = {a0.x, a0.y, a0.z, a0.w, a1.x, a1.y, a1.z, a1.w};
    if (cnt > 0) {
        float inv = 1.f / (float)cnt;
#pragma unroll
        for (int u = 0; u < 8; u++) {
            int ch = choff + u;
            ash[ch * ASTR + r] = fmaf(vals[u] * inv, sc[ch], tc[ch]);
        }
    } else {
#pragma unroll
        for (int u = 0; u < 8; u++) ash[(choff + u) * ASTR + r] = 0.f;
    }
}

// ---------------- layer 1: dual output from one agg ----------------
// Weights: transposed copies in g_wt (slots 0..3: pw1r, pw1l, ew1r, ew1l).
__global__ void __launch_bounds__(128, 8)
k_layer1(const float* __restrict__ pb, const float* __restrict__ eb) {
    const float* pwr = g_wt + 0 * 4096;
    const float* pwl = g_wt + 1 * 4096;
    const float* ewr = g_wt + 2 * 4096;
    const float* ewl = g_wt + 3 * 4096;
    __shared__ float ash[64 * ASTR];
    __shared__ float xsh[64 * ASTR];
    __shared__ float idc[64];
    __shared__ float zc[64];
    __shared__ float sum_p[64], sq_p[64], sum_e[64], sq_e[64];
    int tid = threadIdx.x;
    int row0 = blockIdx.x * TR;

    if (tid < 64) {
        idc[tid] = 1.f; zc[tid] = 0.f;
        sum_p[tid] = 0.f; sq_p[tid] = 0.f; sum_e[tid] = 0.f; sq_e[tid] = 0.f;
    }
    __syncthreads();

    agg_tile(g_x0, row0, ash, idc, zc, tid);
    for (int idx = tid; idx < TR * 64; idx += 128) {
        int k = idx & 63, rr = idx >> 6;
        xsh[k * ASTR + rr] = g_x0[(size_t)(row0 + rr) * 64 + k];
    }
    __syncthreads();

    int cg = tid & 15, rg = tid >> 4;     // 16 colgroups x 8 rowgroups
    int c4 = cg * 4, r2 = rg * 2;
    float accp[2][4] = {}, acce[2][4] = {};
#pragma unroll 4
    for (int k = 0; k < 64; k++) {
        float a0 = ash[k * ASTR + r2];
        float a1 = ash[k * ASTR + r2 + 1];
        float x0 = xsh[k * ASTR + r2];
        float x1 = xsh[k * ASTR + r2 + 1];
        float4 pr = __ldg((const float4*)(pwr + k * 64 + c4));
        float4 pl = __ldg((const float4*)(pwl + k * 64 + c4));
        float4 er = __ldg((const float4*)(ewr + k * 64 + c4));
        float4 el = __ldg((const float4*)(ewl + k * 64 + c4));
        accp[0][0] = fmaf(a0, pr.x, fmaf(x0, pl.x, accp[0][0]));
        accp[0][1] = fmaf(a0, pr.y, fmaf(x0, pl.y, accp[0][1]));
        accp[0][2] = fmaf(a0, pr.z, fmaf(x0, pl.z, accp[0][2]));
        accp[0][3] = fmaf(a0, pr.w, fmaf(x0, pl.w, accp[0][3]));
        accp[1][0] = fmaf(a1, pr.x, fmaf(x1, pl.x, accp[1][0]));
        accp[1][1] = fmaf(a1, pr.y, fmaf(x1, pl.y, accp[1][1]));
        accp[1][2] = fmaf(a1, pr.z, fmaf(x1, pl.z, accp[1][2]));
        accp[1][3] = fmaf(a1, pr.w, fmaf(x1, pl.w, accp[1][3]));
        acce[0][0] = fmaf(a0, er.x, fmaf(x0, el.x, acce[0][0]));
        acce[0][1] = fmaf(a0, er.y, fmaf(x0, el.y, acce[0][1]));
        acce[0][2] = fmaf(a0, er.z, fmaf(x0, el.z, acce[0][2]));
        acce[0][3] = fmaf(a0, er.w, fmaf(x0, el.w, acce[0][3]));
        acce[1][0] = fmaf(a1, er.x, fmaf(x1, el.x, acce[1][0]));
        acce[1][1] = fmaf(a1, er.y, fmaf(x1, el.y, acce[1][1]));
        acce[1][2] = fmaf(a1, er.z, fmaf(x1, el.z, acce[1][2]));
        acce[1][3] = fmaf(a1, er.w, fmaf(x1, el.w, acce[1][3]));
    }
    float psum[4] = {}, psq[4] = {}, esum[4] = {}, esq[4] = {};
#pragma unroll
    for (int ri = 0; ri < 2; ri++) {
        int gr = row0 + r2 + ri;
        float4 op, oe;
        op.x = fmaxf(accp[ri][0] + __ldg(&pb[c4+0]), 0.f);
        op.y = fmaxf(accp[ri][1] + __ldg(&pb[c4+1]), 0.f);
        op.z = fmaxf(accp[ri][2] + __ldg(&pb[c4+2]), 0.f);
        op.w = fmaxf(accp[ri][3] + __ldg(&pb[c4+3]), 0.f);
        oe.x = fmaxf(acce[ri][0] + __ldg(&eb[c4+0]), 0.f);
        oe.y = fmaxf(acce[ri][1] + __ldg(&eb[c4+1]), 0.f);
        oe.z = fmaxf(acce[ri][2] + __ldg(&eb[c4+2]), 0.f);
        oe.w = fmaxf(acce[ri][3] + __ldg(&eb[c4+3]), 0.f);
        *(float4*)&g_p1[(size_t)gr * 64 + c4] = op;
        *(float4*)&g_e1[(size_t)gr * 64 + c4] = oe;
        psum[0]+=op.x; psum[1]+=op.y; psum[2]+=op.z; psum[3]+=op.w;
        psq[0]+=op.x*op.x; psq[1]+=op.y*op.y; psq[2]+=op.z*op.z; psq[3]+=op.w*op.w;
        esum[0]+=oe.x; esum[1]+=oe.y; esum[2]+=oe.z; esum[3]+=oe.w;
        esq[0]+=oe.x*oe.x; esq[1]+=oe.y*oe.y; esq[2]+=oe.z*oe.z; esq[3]+=oe.w*oe.w;
    }
#pragma unroll
    for (int ci = 0; ci < 4; ci++) {
        atomicAdd(&sum_p[c4+ci], psum[ci]); atomicAdd(&sq_p[c4+ci], psq[ci]);
        atomicAdd(&sum_e[c4+ci], esum[ci]); atomicAdd(&sq_e[c4+ci], esq[ci]);
    }
    __syncthreads();
    if (tid < 64) {
        atomicAdd(&g_stats[0][0][tid], sum_p[tid]); atomicAdd(&g_stats[0][1][tid], sq_p[tid]);
        atomicAdd(&g_stats[3][0][tid], sum_e[tid]); atomicAdd(&g_stats[3][1][tid], sq_e[tid]);
    }
}

// ---------------- paired layer jobs, 16-row tiles ----------------
// wr/wl for cout=64 jobs point into g_wt (transposed [k][c]).
// cout=4 job B uses original (4,64) row-major weights (scalar access).
__global__ void __launch_bounds__(128, 10)
k_pair(const float* inA, int sAin, const float* wrA, const float* wlA,
       const float* bA, float* outA, int sAout,
       const float* inB, int sBin, const float* wrB, const float* wlB,
       const float* bB, float* outB, int sBout, int coutB) {
    bool isA = blockIdx.x < GB16;
    int blk = isA ? blockIdx.x : blockIdx.x - GB16;
    const float* in = isA ? inA : inB;
    int s_in  = isA ? sAin : sBin;
    const float* wr = isA ? wrA : wrB;
    const float* wl = isA ? wlA : wlB;
    const float* bias = isA ? bA : bB;
    float* out = isA ? outA : outB;
    int s_out = isA ? sAout : sBout;
    int cout  = isA ? 64 : coutB;

    __shared__ float ash[64 * ASTR];
    __shared__ float xsh[64 * ASTR];
    __shared__ float sc[64], tc[64], ssum[64], ssq[64];
    int tid = threadIdx.x;
    int row0 = blk * TR;

    if (tid < 64) {
        float s, t; bn_coef(s_in, tid, s, t);
        sc[tid] = s; tc[tid] = t;
        ssum[tid] = 0.f; ssq[tid] = 0.f;
    }
    __syncthreads();

    agg_tile(in, row0, ash, sc, tc, tid);
    for (int idx = tid; idx < TR * 64; idx += 128) {
        int k = idx & 63, rr = idx >> 6;
        xsh[k * ASTR + rr] = fmaf(in[(size_t)(row0 + rr) * 64 + k], sc[k], tc[k]);
    }
    __syncthreads();

    if (cout == 64) {
        int cg = tid & 15, rg = tid >> 4;
        int c4 = cg * 4, r2 = rg * 2;
        float acc[2][4] = {};
#pragma unroll 4
        for (int k = 0; k < 64; k++) {
            float a0 = ash[k * ASTR + r2];
            float a1 = ash[k * ASTR + r2 + 1];
            float x0 = xsh[k * ASTR + r2];
            float x1 = xsh[k * ASTR + r2 + 1];
            float4 w4 = __ldg((const float4*)(wr + k * 64 + c4));
            float4 l4 = __ldg((const float4*)(wl + k * 64 + c4));
            acc[0][0] = fmaf(a0, w4.x, fmaf(x0, l4.x, acc[0][0]));
            acc[0][1] = fmaf(a0, w4.y, fmaf(x0, l4.y, acc[0][1]));
            acc[0][2] = fmaf(a0, w4.z, fmaf(x0, l4.z, acc[0][2]));
            acc[0][3] = fmaf(a0, w4.w, fmaf(x0, l4.w, acc[0][3]));
            acc[1][0] = fmaf(a1, w4.x, fmaf(x1, l4.x, acc[1][0]));
            acc[1][1] = fmaf(a1, w4.y, fmaf(x1, l4.y, acc[1][1]));
            acc[1][2] = fmaf(a1, w4.z, fmaf(x1, l4.z, acc[1][2]));
            acc[1][3] = fmaf(a1, w4.w, fmaf(x1, l4.w, acc[1][3]));
        }
        float csum[4] = {}, csq[4] = {};
#pragma unroll
        for (int ri = 0; ri < 2; ri++) {
            int gr = row0 + r2 + ri;
            float v0 = fmaxf(acc[ri][0] + __ldg(&bias[c4+0]), 0.f);
            float v1 = fmaxf(acc[ri][1] + __ldg(&bias[c4+1]), 0.f);
            float v2 = fmaxf(acc[ri][2] + __ldg(&bias[c4+2]), 0.f);
            float v3 = fmaxf(acc[ri][3] + __ldg(&bias[c4+3]), 0.f);
            float4 o; o.x = v0; o.y = v1; o.z = v2; o.w = v3;
            *(float4*)&out[(size_t)gr * 64 + c4] = o;
            csum[0]+=v0; csum[1]+=v1; csum[2]+=v2; csum[3]+=v3;
            csq[0]+=v0*v0; csq[1]+=v1*v1; csq[2]+=v2*v2; csq[3]+=v3*v3;
        }
#pragma unroll
        for (int ci = 0; ci < 4; ci++) {
            atomicAdd(&ssum[c4+ci], csum[ci]);
            atomicAdd(&ssq[c4+ci], csq[ci]);
        }
        __syncthreads();
        if (tid < 64) {
            atomicAdd(&g_stats[s_out][0][tid], ssum[tid]);
            atomicAdd(&g_stats[s_out][1][tid], ssq[tid]);
        }
    } else {
        // cout == 4: 16 rows x 4 cols = 64 active threads; W is (4,64) row-major
        if (tid < 64) {
            int r = tid >> 2, c = tid & 3;
            int gr = row0 + r;
            float acc = 0.f;
#pragma unroll 8
            for (int k = 0; k < 64; k++)
                acc = fmaf(ash[k*ASTR+r], __ldg(&wr[c*64 + k]),
                      fmaf(xsh[k*ASTR+r], __ldg(&wl[c*64 + k]), acc));
            float v = fmaxf(acc + __ldg(&bias[c]), 0.f);
            out[(size_t)gr * 4 + c] = v;
            atomicAdd(&ssum[c], v);
            atomicAdd(&ssq[c], v * v);
        }
        __syncthreads();
        if (tid < 4) {
            atomicAdd(&g_stats[s_out][0][tid], ssum[tid]);
            atomicAdd(&g_stats[s_out][1][tid], ssq[tid]);
        }
    }
}

// ---------------- pool assignment + x_embed ----------------
__global__ void k_pool_xemb(const float* __restrict__ plw, const float* __restrict__ plb,
                            const float* __restrict__ ew, const float* __restrict__ eb) {
    __shared__ float ws[192 * 33];
    __shared__ float s1[64], t1[64], s2[64], t2[64], s3[4], t3[4];
    __shared__ float se[192], te[192];
    int tid = threadIdx.x;

    if (blockIdx.x < 750) {
        if (tid < 64)       { float s,t; bn_coef(0, tid, s, t);      s1[tid]=s; t1[tid]=t; }
        else if (tid < 128) { float s,t; bn_coef(1, tid-64, s, t);   s2[tid-64]=s; t2[tid-64]=t; }
        else if (tid < 132) { float s,t; bn_coef(2, tid-128, s, t);  s3[tid-128]=s; t3[tid-128]=t; }
        __syncthreads();
        int i = blockIdx.x * 8 + (tid >> 5);
        int lane = tid & 31;
        float a0 = 0.f, a1 = 0.f, a2 = 0.f, a3 = 0.f;
        for (int k = lane; k < 64; k += 32) {
            float v1 = fmaf(g_p1[(size_t)i*64+k], s1[k], t1[k]);
            float v2 = fmaf(g_p2[(size_t)i*64+k], s2[k], t2[k]);
            a0 += v1 * plw[0*132+k] + v2 * plw[0*132+64+k];
            a1 += v1 * plw[1*132+k] + v2 * plw[1*132+64+k];
            a2 += v1 * plw[2*132+k] + v2 * plw[2*132+64+k];
            a3 += v1 * plw[3*132+k] + v2 * plw[3*132+64+k];
        }
        if (lane < 4) {
            float v3 = fmaf(g_p3[(size_t)i*4+lane], s3[lane], t3[lane]);
            a0 += v3 * plw[0*132+128+lane];
            a1 += v3 * plw[1*132+128+lane];
            a2 += v3 * plw[2*132+128+lane];
            a3 += v3 * plw[3*132+128+lane];
        }
#pragma unroll
        for (int o = 16; o > 0; o >>= 1) {
            a0 += __shfl_xor_sync(0xFFFFFFFFu, a0, o);
            a1 += __shfl_xor_sync(0xFFFFFFFFu, a1, o);
            a2 += __shfl_xor_sync(0xFFFFFFFFu, a2, o);
            a3 += __shfl_xor_sync(0xFFFFFFFFu, a3, o);
        }
        if (lane == 0) {
            float q0 = fmaxf(a0 + plb[0], 0.f), q1 = fmaxf(a1 + plb[1], 0.f);
            float q2 = fmaxf(a2 + plb[2], 0.f), q3 = fmaxf(a3 + plb[3], 0.f);
            int am = 0; float best = q0;
            if (q1 > best) { best = q1; am = 1; }
            if (q2 > best) { best = q2; am = 2; }
            if (q3 > best) { best = q3; am = 3; }
            g_am[i] = am;
            float e0 = expf(q0-best), e1 = expf(q1-best), e2 = expf(q2-best), e3 = expf(q3-best);
            float inv = 1.f / (e0+e1+e2+e3);
            g_ssm[i*4+0] = e0*inv; g_ssm[i*4+1] = e1*inv;
            g_ssm[i*4+2] = e2*inv; g_ssm[i*4+3] = e3*inv;
        }
    } else {
        if (tid < 192) {
            float s, t; bn_coef(3 + tid / 64, tid & 63, s, t);
            se[tid] = s; te[tid] = t;
        }
        for (int idx = tid; idx < 6144; idx += 256) {
            int c = idx / 192, k = idx % 192;
            ws[k * 33 + c] = ew[idx];
        }
        __syncthreads();
        int blk = blockIdx.x - 750;
        int c = tid & 31, r0t = tid >> 5;
        int row0 = blk * 64;
        for (int r = r0t; r < 64; r += 8) {
            int gr = row0 + r;
            if (gr >= NN) continue;
            float acc = eb[c];
            const float* p1 = &g_e1[(size_t)gr * 64];
            const float* p2 = &g_e2[(size_t)gr * 64];
            const float* p3 = &g_e3[(size_t)gr * 64];
#pragma unroll 8
            for (int k = 0; k < 64; k++) {
                acc = fmaf(fmaf(p1[k], se[k],     te[k]),     ws[k*33+c],       acc);
                acc = fmaf(fmaf(p2[k], se[64+k],  te[64+k]),  ws[(64+k)*33+c],  acc);
                acc = fmaf(fmaf(p3[k], se[128+k], te[128+k]), ws[(128+k)*33+c], acc);
            }
            g_xemb[(size_t)gr * 32 + c] = acc;
        }
    }
}

__global__ void k_sxacc() {
    int c = threadIdx.x;
    int slot = 3 + c / 64, co = c & 63;
    float s, t; bn_coef(slot, co, s, t);
    const float* src = (c < 64) ? g_e1 : (c < 128) ? g_e2 : g_e3;
    int n0 = blockIdx.x * 125;
    float a0 = 0.f, a1 = 0.f, a2 = 0.f, a3 = 0.f;
    for (int n = n0; n < n0 + 125; n++) {
        float w0 = g_ssm[n*4+0], w1 = g_ssm[n*4+1], w2 = g_ssm[n*4+2], w3 = g_ssm[n*4+3];
        float v = fmaf(src[(size_t)n * 64 + co], s, t);
        a0 = fmaf(w0, v, a0); a1 = fmaf(w1, v, a1);
        a2 = fmaf(w2, v, a2); a3 = fmaf(w3, v, a3);
    }
    atomicAdd(&g_sx[0*192+c], a0);
    atomicAdd(&g_sx[1*192+c], a1);
    atomicAdd(&g_sx[2*192+c], a2);
    atomicAdd(&g_sx[3*192+c], a3);
}

__global__ void k_head(const float* __restrict__ l1w, const float* __restrict__ l1b,
                       const float* __restrict__ l2w, const float* __restrict__ l2b) {
    __shared__ float t1[4][64];
    int tid = threadIdx.x;
    int j = tid >> 6, c = tid & 63;
    float acc = l1b[c];
#pragma unroll 8
    for (int k = 0; k < 192; k++) acc = fmaf(g_sx[j*192+k], l1w[c*192+k], acc);
    t1[j][c] = fmaxf(acc, 0.f);
    __syncthreads();
    if (tid < 64) {
        int jj = tid >> 4, cc = tid & 15;
        float a = l2b[cc];
#pragma unroll
        for (int k = 0; k < 64; k++) a = fmaf(t1[jj][k], l2w[cc*64+k], a);
        g_sx2[jj*16+cc] = a;
    }
}

__global__ void k_final(const float* __restrict__ l3w, const float* __restrict__ l3b,
                        float* __restrict__ out) {
    __shared__ float w[768];
    __shared__ float b[16];
    __shared__ float sx2[64];
    int tid = threadIdx.x;
    for (int idx = tid; idx < 768; idx += 256) w[idx] = l3w[idx];
    if (tid < 16) b[tid] = l3b[tid];
    if (tid < 64) sx2[tid] = g_sx2[tid];
    __syncthreads();
    int c = tid & 15, ln = tid >> 4;
    int i = blockIdx.x * 16 + ln;
    int am = g_am[i];
    float acc = b[c];
    const float* xe = &g_xemb[(size_t)i * 32];
#pragma unroll
    for (int k = 0; k < 32; k++) acc = fmaf(xe[k], w[c*48+k], acc);
#pragma unroll
    for (int k = 0; k < 16; k++) acc = fmaf(sx2[am*16+k], w[c*48+32+k], acc);
    out[(size_t)i * 16 + c] = acc;
}

// ---------------- host ----------------
extern "C" void kernel_launch(void* const* d_in, const int* in_sizes, int n_in,
                              void* d_out, int out_size) {
    const int* ei = nullptr;
    const int* nt = nullptr;
    const float* P[29];
    int np = 0;
    for (int i = 0; i < n_in; i++) {
        if (in_sizes[i] == 2 * EE)      ei = (const int*)d_in[i];
        else if (in_sizes[i] == NN)     nt = (const int*)d_in[i];
        else if (np < 29)               P[np++] = (const float*)d_in[i];
    }
    if (!ei || !nt || np != 29) return;

    const float *emb  = P[0];
    const float *pw1r = P[1],  *pw1l = P[2],  *pb1 = P[3];
    const float *pw2r = P[4],  *pw2l = P[5],  *pb2 = P[6];
    const float *pw3r = P[7],  *pw3l = P[8],  *pb3 = P[9];
    const float *plw  = P[10], *plb  = P[11];
    const float *ew1r = P[12], *ew1l = P[13], *eb1 = P[14];
    const float *ew2r = P[15], *ew2l = P[16], *eb2 = P[17];
    const float *ew3r = P[18], *ew3l = P[19], *eb3 = P[20];
    const float *l1w  = P[21], *l1b  = P[22];
    const float *l2w  = P[23], *l2b  = P[24];
    const float *emblw = P[25], *emblb = P[26];
    const float *l3w  = P[27], *l3b  = P[28];
    float* out = (float*)d_out;

    static float *p_p1 = nullptr, *p_p2, *p_p3, *p_e1, *p_e2, *p_e3, *p_wt;
    if (!p_p1) {
        cudaGetSymbolAddress((void**)&p_p1, g_p1);
        cudaGetSymbolAddress((void**)&p_p2, g_p2);
        cudaGetSymbolAddress((void**)&p_p3, g_p3);
        cudaGetSymbolAddress((void**)&p_e1, g_e1);
        cudaGetSymbolAddress((void**)&p_e2, g_e2);
        cudaGetSymbolAddress((void**)&p_e3, g_e3);
        cudaGetSymbolAddress((void**)&p_wt, g_wt);
    }

    // init + transpose weights (slots: 0 pw1r, 1 pw1l, 2 ew1r, 3 ew1l,
    //                                  4 pw2r, 5 pw2l, 6 ew2r, 7 ew2l, 8 ew3r, 9 ew3l)
    k_init<<<190, 256>>>(pw1r, pw1l, ew1r, ew1l, pw2r, pw2l, ew2r, ew2l, ew3r, ew3l);
    k_build_gather<<<2250, 256>>>(ei, emb, nt);
    // layer 1: one agg, both outputs
    k_layer1<<<GB16, 128>>>(pb1, eb1);
    // layer 2 (pool + embed), transposed weights from g_wt
    k_pair<<<2 * GB16, 128>>>(p_p1, 0, p_wt + 4*4096, p_wt + 5*4096, pb2, p_p2, 1,
                              p_e1, 3, p_wt + 6*4096, p_wt + 7*4096, eb2, p_e2, 4, 64);
    // layer 3 (embed cout=64 + pool cout=4; pool uses original row-major weights)
    k_pair<<<2 * GB16, 128>>>(p_e2, 4, p_wt + 8*4096, p_wt + 9*4096, eb3, p_e3, 5,
                              p_p2, 1, pw3r, pw3l, pb3, p_p3, 2, 4);
    k_pool_xemb<<<750 + GB64, 256>>>(plw, plb, emblw, emblb);
    k_sxacc<<<48, 192>>>();
    k_head<<<1, 256>>>(l1w, l1b, l2w, l2b);
    k_final<<<NN / 16, 256>>>(l3w, l3b, out);
}